// round 16
// baseline (speedup 1.0000x reference)
#include <cuda_runtime.h>
#include <cuda_fp16.h>
#include <cuda_bf16.h>
#include <cstdint>

// Problem constants (from reference)
#define N_PTS 50000
#define CH    64
#define KNN   16
#define NBR   3      // dilation branches (1,2,4)
#define NCLOUD 25
#define PTS_PER_CLOUD 2000
#define KMAX  64
#define NTILE128 ((N_PTS + 127) / 128)   // 391
#define GEMM_GRID_X 98                   // each block sweeps ceil(391/98)=4 tiles

#define NEG_BIG (-1e30f)

// Scratch (device globals -- allocation-free rule)
// Packed K/V: for node n, branch b, channel c: g_KV[(n*3+b)*64 + c] = half2(k, v)
__device__ __half2 g_KV[(size_t)N_PTS * NBR * CH];
__device__ float   g_pool[NCLOUD * CH];     // per-cloud max of x

// ---------------------------------------------------------------------------
// Warp-level fp16 tensor-core MMA: D[16x8] += A[16x16] * B[16x8], fp32 accum.
// ---------------------------------------------------------------------------
__device__ __forceinline__ void mma_16816(float c[4],
                                          uint32_t a0, uint32_t a1, uint32_t a2, uint32_t a3,
                                          uint32_t b0, uint32_t b1)
{
    asm volatile(
        "mma.sync.aligned.m16n8k16.row.col.f32.f16.f16.f32 "
        "{%0,%1,%2,%3}, {%4,%5,%6,%7}, {%8,%9}, {%0,%1,%2,%3};\n"
        : "+f"(c[0]), "+f"(c[1]), "+f"(c[2]), "+f"(c[3])
        : "r"(a0), "r"(a1), "r"(a2), "r"(a3), "r"(b0), "r"(b1));
}

// ---------------------------------------------------------------------------
// Kernel 1: fused K+V GEMM per branch on tensor cores, PERSISTENT over tiles.
// grid = (98, 3), block = 256 (8 warps).  Weights loaded+transposed to smem
// ONCE per block; block sweeps ~4 tiles of 128 rows.
// ---------------------------------------------------------------------------
__global__ __launch_bounds__(256) void gemm_kv_kernel(
    const float* __restrict__ x,
    const float* __restrict__ Wv,
    const float* __restrict__ Wk)
{
    const int b = blockIdx.y;            // branch 0..2

    __shared__ __half xs[128][72];       // 18432 B
    __shared__ __half wt[2][64][72];     // 18432 B   [mat][n][k]

    const int tid = threadIdx.x;

    // --- Load + transpose both weight matrices into smem fp16 (n-major), once ---
    {
        const float4* wk4 = (const float4*)(Wk + b * CH * CH);
        const float4* wv4 = (const float4*)(Wv + b * CH * CH);
        for (int i = tid; i < CH * CH / 4; i += 256) {
            const int k  = i >> 4;
            const int n0 = (i & 15) * 4;
            float4 a = wk4[i];
            wt[0][n0 + 0][k] = __float2half(a.x);
            wt[0][n0 + 1][k] = __float2half(a.y);
            wt[0][n0 + 2][k] = __float2half(a.z);
            wt[0][n0 + 3][k] = __float2half(a.w);
            float4 v = wv4[i];
            wt[1][n0 + 0][k] = __float2half(v.x);
            wt[1][n0 + 1][k] = __float2half(v.y);
            wt[1][n0 + 2][k] = __float2half(v.z);
            wt[1][n0 + 3][k] = __float2half(v.w);
        }
    }

    const int warp  = tid >> 5;
    const int lane  = tid & 31;
    const int group = lane >> 2;        // 0..7
    const int tid4  = lane & 3;         // 0..3
    const int rbase = warp * 16;        // warp's row tile inside the block

    for (int tile = blockIdx.x; tile < NTILE128; tile += GEMM_GRID_X) {
        const int row0 = tile * 128;

        __syncthreads();   // prev tile readers done; also fences wt stores (1st iter)

        // --- Load x tile (128 rows x 64 ch), convert fp32 -> fp16 ---
        for (int i = tid; i < 128 * (CH / 4); i += 256) {
            const int r  = i >> 4;
            const int c4 = i & 15;
            float4 v = make_float4(0.f, 0.f, 0.f, 0.f);
            if (row0 + r < N_PTS)
                v = ((const float4*)x)[(size_t)(row0 + r) * (CH / 4) + c4];
            __half2 lo = __float22half2_rn(make_float2(v.x, v.y));
            __half2 hi = __float22half2_rn(make_float2(v.z, v.w));
            *(uint32_t*)&xs[r][c4 * 4 + 0] = *(uint32_t*)&lo;
            *(uint32_t*)&xs[r][c4 * 4 + 2] = *(uint32_t*)&hi;
        }
        __syncthreads();

        float cK[8][4], cV[8][4];
        #pragma unroll
        for (int nt = 0; nt < 8; nt++)
            #pragma unroll
            for (int jj = 0; jj < 4; jj++) { cK[nt][jj] = 0.f; cV[nt][jj] = 0.f; }

        #pragma unroll
        for (int ch = 0; ch < 4; ch++) {            // k chunks of 16
            const int k0 = ch * 16;
            const uint32_t a0 = *(const uint32_t*)&xs[rbase + group    ][k0 + 2 * tid4];
            const uint32_t a1 = *(const uint32_t*)&xs[rbase + group + 8][k0 + 2 * tid4];
            const uint32_t a2 = *(const uint32_t*)&xs[rbase + group    ][k0 + 2 * tid4 + 8];
            const uint32_t a3 = *(const uint32_t*)&xs[rbase + group + 8][k0 + 2 * tid4 + 8];

            #pragma unroll
            for (int nt = 0; nt < 8; nt++) {
                const int n = nt * 8 + group;
                const uint32_t bk0 = *(const uint32_t*)&wt[0][n][k0 + 2 * tid4];
                const uint32_t bk1 = *(const uint32_t*)&wt[0][n][k0 + 2 * tid4 + 8];
                const uint32_t bv0 = *(const uint32_t*)&wt[1][n][k0 + 2 * tid4];
                const uint32_t bv1 = *(const uint32_t*)&wt[1][n][k0 + 2 * tid4 + 8];
                mma_16816(cK[nt], a0, a1, a2, a3, bk0, bk1);
                mma_16816(cV[nt], a0, a1, a2, a3, bv0, bv1);
            }
        }

        // --- Epilogue: pack half2(k,v) and store 8B per (row, col-pair) ---
        const int row_lo = row0 + rbase + group;
        const int row_hi = row_lo + 8;
        #pragma unroll
        for (int nt = 0; nt < 8; nt++) {
            const int col = nt * 8 + 2 * tid4;      // channel pair base
            if (row_lo < N_PTS) {
                __half2 p0 = __float22half2_rn(make_float2(cK[nt][0], cV[nt][0]));
                __half2 p1 = __float22half2_rn(make_float2(cK[nt][1], cV[nt][1]));
                uint2 pk = make_uint2(*(uint32_t*)&p0, *(uint32_t*)&p1);
                *(uint2*)(g_KV + ((size_t)row_lo * NBR + b) * CH + col) = pk;
            }
            if (row_hi < N_PTS) {
                __half2 p0 = __float22half2_rn(make_float2(cK[nt][2], cV[nt][2]));
                __half2 p1 = __float22half2_rn(make_float2(cK[nt][3], cV[nt][3]));
                uint2 pk = make_uint2(*(uint32_t*)&p0, *(uint32_t*)&p1);
                *(uint2*)(g_KV + ((size_t)row_hi * NBR + b) * CH + col) = pk;
            }
        }
    }
}

// ---------------------------------------------------------------------------
// Kernel 2: per-cloud channel-wise max pool.  grid = 25, block = 1024
// ---------------------------------------------------------------------------
__global__ __launch_bounds__(1024) void pool_kernel(const float* __restrict__ x)
{
    __shared__ float red[1024];
    const int cloud = blockIdx.x;
    const int c   = threadIdx.x & 63;
    const int seg = threadIdx.x >> 6;
    const int base = cloud * PTS_PER_CLOUD + seg * (PTS_PER_CLOUD / 16);

    float m = NEG_BIG;
    #pragma unroll 5
    for (int i = 0; i < PTS_PER_CLOUD / 16; i++)
        m = fmaxf(m, x[(size_t)(base + i) * CH + c]);

    red[threadIdx.x] = m;
    __syncthreads();
    if (seg == 0) {
        #pragma unroll
        for (int s = 1; s < 16; s++) m = fmaxf(m, red[s * 64 + c]);
        g_pool[cloud * CH + c] = m;
    }
}

// ---------------------------------------------------------------------------
// Edge slot map: the 3 dilated branches use only 32 DISTINCT edges per node:
//   lanes  0..15 own edges  l          (0..15)
//   lanes 16..23 own edges  2l-16      (16,18,..,30)
//   lanes 24..31 own edges  4l-64      (32,36,..,60)
// slot_of(b,t) returns the owning lane of branch b's t-th edge (t*dil).
// ---------------------------------------------------------------------------
__device__ constexpr int slot_of(int b, int t) {
    return b == 0 ? t
         : b == 1 ? (t < 8 ? 2 * t : t + 8)
         : (t < 4 ? 4 * t : (t < 8 ? 2 * t + 8 : t + 16));
}

// ---------------------------------------------------------------------------
// Kernel 3: fused attention, single-pass softmax, smem edge table.
// One warp per node (block = 8 nodes).  Unified prologue builds 32-entry
// (offset,dx,dy,dz) table; main loop does 1 broadcast LDS.128 per step
// instead of 4 shuffles + 3 subs.  q_i cancels in softmax -> Wq unused.
// ---------------------------------------------------------------------------
__global__ __launch_bounds__(256) void edge_kernel(
    const float* __restrict__ x,
    const float* __restrict__ pos,
    const float* __restrict__ Wp,      // [3][3][64]
    const float* __restrict__ bp,      // [3][64]
    const int*   __restrict__ ei,      // edge_index row0 (src), length N*KMAX
    const int*   __restrict__ batch,
    float*       __restrict__ out)
{
    __shared__ float4 etab[8][32];

    const int warp = threadIdx.x >> 5;
    const int lane = threadIdx.x & 31;
    const int n    = blockIdx.x * 8 + warp;    // grid is exact: 6250*8 = 50000
    const int c0   = lane * 2;

    // --- Unified prologue: each lane owns one of the 32 distinct edges ---
    {
        const int e = (lane < 16) ? lane : (lane < 24 ? 2 * lane - 16 : 4 * lane - 64);
        const int j = ei[(size_t)n * KMAX + e];
        float4 et;
        et.x = __int_as_float(j * (NBR * CH));      // element offset into g_KV
        et.y = pos[n * 3 + 0] - pos[j * 3 + 0];
        et.z = pos[n * 3 + 1] - pos[j * 3 + 1];
        et.w = pos[n * 3 + 2] - pos[j * 3 + 2];
        etab[warp][lane] = et;
    }
    __syncwarp();

    const float2 xv = *(const float2*)(x + (size_t)n * CH + c0);

    float2 best = make_float2(NEG_BIG, NEG_BIG);

    #pragma unroll
    for (int b = 0; b < NBR; b++) {
        const float* Wpb = Wp + b * 3 * CH;
        const float2 w0  = *(const float2*)(Wpb + 0 * CH + c0);
        const float2 w1  = *(const float2*)(Wpb + 1 * CH + c0);
        const float2 w2  = *(const float2*)(Wpb + 2 * CH + c0);
        const float2 bpv = *(const float2*)(bp + b * CH + c0);
        const int    bC  = b * CH + c0;

        float2 sum = make_float2(0.f, 0.f);
        float2 acc = make_float2(0.f, 0.f);

        #pragma unroll
        for (int t = 0; t < KNN; t++) {
            const float4 et = etab[warp][slot_of(b, t)];   // broadcast LDS.128
            const int off = __float_as_int(et.x) + bC;

            // one 8B load fetches (k,v) for both channels
            const uint2 raw = *(const uint2*)(g_KV + off);
            const float2 kv0 = __half22float2(*(const __half2*)&raw.x);  // (k,v) @ c0
            const float2 kv1 = __half22float2(*(const __half2*)&raw.y);  // (k,v) @ c0+1

            const float delx = fmaf(et.y, w0.x, fmaf(et.z, w1.x, fmaf(et.w, w2.x, bpv.x)));
            const float dely = fmaf(et.y, w0.y, fmaf(et.z, w1.y, fmaf(et.w, w2.y, bpv.y)));

            const float ex = __expf(delx - kv0.x);
            const float ey = __expf(dely - kv1.x);
            sum.x += ex;
            sum.y += ey;
            acc.x = fmaf(ex, kv0.y + delx, acc.x);
            acc.y = fmaf(ey, kv1.y + dely, acc.y);
        }

        const float hx = acc.x / (sum.x + 1e-16f);
        const float hy = acc.y / (sum.y + 1e-16f);
        best.x = fmaxf(best.x, hx);
        best.y = fmaxf(best.y, hy);
    }

    const int cloud = batch[n];
    const float2 p = *(const float2*)(g_pool + cloud * CH + c0);

    float2 o;
    o.x = fmaxf(best.x, p.x) + xv.x;
    o.y = fmaxf(best.y, p.y) + xv.y;
    *(float2*)(out + (size_t)n * CH + c0) = o;
}

// ---------------------------------------------------------------------------
// Launch.  Inputs (metadata order):
//  0: x[N*64] f32, 1: pos[N*3] f32, 2: Wv[3*64*64], 3: Wq (UNUSED),
//  4: Wk[3*64*64], 5: Wp[3*3*64], 6: bp[3*64],
//  7: edge_index[2*N*64] i32, 8: batch[N] i32
// ---------------------------------------------------------------------------
extern "C" void kernel_launch(void* const* d_in, const int* in_sizes, int n_in,
                              void* d_out, int out_size)
{
    (void)in_sizes; (void)n_in; (void)out_size;
    const float* x   = (const float*)d_in[0];
    const float* pos = (const float*)d_in[1];
    const float* Wv  = (const float*)d_in[2];
    const float* Wk  = (const float*)d_in[4];
    const float* Wp  = (const float*)d_in[5];
    const float* bp  = (const float*)d_in[6];
    const int*   ei  = (const int*)d_in[7];      // row0 = src
    const int*   bat = (const int*)d_in[8];
    float* out = (float*)d_out;

    dim3 ggrid(GEMM_GRID_X, NBR);
    gemm_kv_kernel<<<ggrid, 256>>>(x, Wv, Wk);

    pool_kernel<<<NCLOUD, 1024>>>(x);

    edge_kernel<<<N_PTS / 8, 256>>>(x, pos, Wp, bp, ei, bat, out);
}

// round 17
// speedup vs baseline: 1.5844x; 1.5844x over previous
#include <cuda_runtime.h>
#include <cuda_fp16.h>
#include <cuda_bf16.h>
#include <cstdint>

// Problem constants (from reference)
#define N_PTS 50000
#define CH    64
#define KNN   16
#define NBR   3      // dilation branches (1,2,4)
#define NCLOUD 25
#define PTS_PER_CLOUD 2000
#define KMAX  64

#define NEG_BIG (-1e30f)

// Scratch (device globals -- allocation-free rule)
// Packed K'/V': for node n, branch b, channel c: g_KV[(n*3+b)*64+c] = half2(k', v')
//   k' = (x@Wk + pos@Wp)[c],  v' = (x@Wv - pos@Wp)[c]
__device__ __half2 g_KV[(size_t)N_PTS * NBR * CH];
__device__ float   g_pool[NCLOUD * CH];     // per-cloud max of x

// ---------------------------------------------------------------------------
// Warp-level fp16 tensor-core MMA: D[16x8] += A[16x16] * B[16x8], fp32 accum.
// ---------------------------------------------------------------------------
__device__ __forceinline__ void mma_16816(float c[4],
                                          uint32_t a0, uint32_t a1, uint32_t a2, uint32_t a3,
                                          uint32_t b0, uint32_t b1)
{
    asm volatile(
        "mma.sync.aligned.m16n8k16.row.col.f32.f16.f16.f32 "
        "{%0,%1,%2,%3}, {%4,%5,%6,%7}, {%8,%9}, {%0,%1,%2,%3};\n"
        : "+f"(c[0]), "+f"(c[1]), "+f"(c[2]), "+f"(c[3])
        : "r"(a0), "r"(a1), "r"(a2), "r"(a3), "r"(b0), "r"(b1));
}

// ---------------------------------------------------------------------------
// Kernel 1: fused K'+V' GEMM per branch on tensor cores.
// grid = (ceil(N/128), 3), block = 256 (8 warps); non-persistent (best config).
// K dim extended to 80: rows 0..63 = x (vs Wk/Wv), rows 64..66 = pos
// (vs +Wp for K', -Wp for V'), rows 67..79 = zero pad.
// smem stride 88 halfs -> fragment loads hit all 32 banks exactly once.
// ---------------------------------------------------------------------------
__global__ __launch_bounds__(256) void gemm_kv_kernel(
    const float* __restrict__ x,
    const float* __restrict__ pos,
    const float* __restrict__ Wv,
    const float* __restrict__ Wk,
    const float* __restrict__ Wp)
{
    const int b = blockIdx.y;            // branch 0..2

    __shared__ __half xs[128][88];       // 22528 B
    __shared__ __half wt[2][64][88];     // 22528 B   [mat][n][k]

    const int tid  = threadIdx.x;
    const int row0 = blockIdx.x * 128;

    // --- Weights: rows 0..63 from Wk/Wv (transposed to n-major) ---
    {
        const float4* wk4 = (const float4*)(Wk + b * CH * CH);
        const float4* wv4 = (const float4*)(Wv + b * CH * CH);
        for (int i = tid; i < CH * CH / 4; i += 256) {
            const int k  = i >> 4;
            const int n0 = (i & 15) * 4;
            float4 a = wk4[i];
            wt[0][n0 + 0][k] = __float2half(a.x);
            wt[0][n0 + 1][k] = __float2half(a.y);
            wt[0][n0 + 2][k] = __float2half(a.z);
            wt[0][n0 + 3][k] = __float2half(a.w);
            float4 v = wv4[i];
            wt[1][n0 + 0][k] = __float2half(v.x);
            wt[1][n0 + 1][k] = __float2half(v.y);
            wt[1][n0 + 2][k] = __float2half(v.z);
            wt[1][n0 + 3][k] = __float2half(v.w);
        }
        // rows 64..79: +Wp / -Wp for r<3, zero pad beyond
        for (int i = tid; i < CH * 16; i += 256) {
            const int n  = i >> 4;
            const int kk = 64 + (i & 15);
            float w = 0.f;
            if ((i & 15) < 3) w = Wp[b * 3 * CH + (i & 15) * CH + n];
            wt[0][n][kk] = __float2half(w);
            wt[1][n][kk] = __float2half(-w);
        }
    }

    // --- x tile: cols 0..63 = features, 64..66 = pos, 67..79 = 0 ---
    for (int i = tid; i < 128 * (CH / 4); i += 256) {
        const int r  = i >> 4;
        const int c4 = i & 15;
        float4 v = make_float4(0.f, 0.f, 0.f, 0.f);
        if (row0 + r < N_PTS)
            v = ((const float4*)x)[(size_t)(row0 + r) * (CH / 4) + c4];
        __half2 lo = __float22half2_rn(make_float2(v.x, v.y));
        __half2 hi = __float22half2_rn(make_float2(v.z, v.w));
        *(uint32_t*)&xs[r][c4 * 4 + 0] = *(uint32_t*)&lo;
        *(uint32_t*)&xs[r][c4 * 4 + 2] = *(uint32_t*)&hi;
    }
    for (int i = tid; i < 128 * 16; i += 256) {
        const int r  = i >> 4;
        const int kk = 64 + (i & 15);
        float v = 0.f;
        if ((i & 15) < 3 && row0 + r < N_PTS) v = pos[(size_t)(row0 + r) * 3 + (i & 15)];
        xs[r][kk] = __float2half(v);
    }
    __syncthreads();

    const int warp  = tid >> 5;
    const int lane  = tid & 31;
    const int group = lane >> 2;        // 0..7
    const int tid4  = lane & 3;         // 0..3
    const int rbase = warp * 16;        // warp's row tile inside the block

    float cK[8][4], cV[8][4];
    #pragma unroll
    for (int nt = 0; nt < 8; nt++)
        #pragma unroll
        for (int jj = 0; jj < 4; jj++) { cK[nt][jj] = 0.f; cV[nt][jj] = 0.f; }

    #pragma unroll
    for (int ch = 0; ch < 5; ch++) {            // k chunks of 16 (80 total)
        const int k0 = ch * 16;
        const uint32_t a0 = *(const uint32_t*)&xs[rbase + group    ][k0 + 2 * tid4];
        const uint32_t a1 = *(const uint32_t*)&xs[rbase + group + 8][k0 + 2 * tid4];
        const uint32_t a2 = *(const uint32_t*)&xs[rbase + group    ][k0 + 2 * tid4 + 8];
        const uint32_t a3 = *(const uint32_t*)&xs[rbase + group + 8][k0 + 2 * tid4 + 8];

        #pragma unroll
        for (int nt = 0; nt < 8; nt++) {
            const int n = nt * 8 + group;
            const uint32_t bk0 = *(const uint32_t*)&wt[0][n][k0 + 2 * tid4];
            const uint32_t bk1 = *(const uint32_t*)&wt[0][n][k0 + 2 * tid4 + 8];
            const uint32_t bv0 = *(const uint32_t*)&wt[1][n][k0 + 2 * tid4];
            const uint32_t bv1 = *(const uint32_t*)&wt[1][n][k0 + 2 * tid4 + 8];
            mma_16816(cK[nt], a0, a1, a2, a3, bk0, bk1);
            mma_16816(cV[nt], a0, a1, a2, a3, bv0, bv1);
        }
    }

    // --- Epilogue: pack half2(k',v') and store 8B per (row, col-pair) ---
    const int row_lo = row0 + rbase + group;
    const int row_hi = row_lo + 8;
    #pragma unroll
    for (int nt = 0; nt < 8; nt++) {
        const int col = nt * 8 + 2 * tid4;      // channel pair base
        if (row_lo < N_PTS) {
            __half2 p0 = __float22half2_rn(make_float2(cK[nt][0], cV[nt][0]));
            __half2 p1 = __float22half2_rn(make_float2(cK[nt][1], cV[nt][1]));
            uint2 pk = make_uint2(*(uint32_t*)&p0, *(uint32_t*)&p1);
            *(uint2*)(g_KV + ((size_t)row_lo * NBR + b) * CH + col) = pk;
        }
        if (row_hi < N_PTS) {
            __half2 p0 = __float22half2_rn(make_float2(cK[nt][2], cV[nt][2]));
            __half2 p1 = __float22half2_rn(make_float2(cK[nt][3], cV[nt][3]));
            uint2 pk = make_uint2(*(uint32_t*)&p0, *(uint32_t*)&p1);
            *(uint2*)(g_KV + ((size_t)row_hi * NBR + b) * CH + col) = pk;
        }
    }
}

// ---------------------------------------------------------------------------
// Kernel 2: per-cloud channel-wise max pool.  grid = 25, block = 1024
// ---------------------------------------------------------------------------
__global__ __launch_bounds__(1024) void pool_kernel(const float* __restrict__ x)
{
    __shared__ float red[1024];
    const int cloud = blockIdx.x;
    const int c   = threadIdx.x & 63;
    const int seg = threadIdx.x >> 6;
    const int base = cloud * PTS_PER_CLOUD + seg * (PTS_PER_CLOUD / 16);

    float m = NEG_BIG;
    #pragma unroll 5
    for (int i = 0; i < PTS_PER_CLOUD / 16; i++)
        m = fmaxf(m, x[(size_t)(base + i) * CH + c]);

    red[threadIdx.x] = m;
    __syncthreads();
    if (seg == 0) {
        #pragma unroll
        for (int s = 1; s < 16; s++) m = fmaxf(m, red[s * 64 + c]);
        g_pool[cloud * CH + c] = m;
    }
}

// ---------------------------------------------------------------------------
// Kernel 3: fused attention, single-pass softmax, positional math factored out:
//   score_ij = A_i - K'_j      A_i = pos_i@Wp + bp   (computed once per node)
//   value_ij = V'_j + A_i      K'_j,V'_j precomputed by the GEMM
// Inner step: 1 shuffle + 1 LDG.64 + exp + 4 adds/fmas.  Wq cancels.
// One warp per node; lane handles channels (2*lane, 2*lane+1).
// ---------------------------------------------------------------------------
__global__ __launch_bounds__(256) void edge_kernel(
    const float* __restrict__ x,
    const float* __restrict__ pos,
    const float* __restrict__ Wp,      // [3][3][64]
    const float* __restrict__ bp,      // [3][64]
    const int*   __restrict__ ei,      // edge_index row0 (src), length N*KMAX
    const int*   __restrict__ batch,
    float*       __restrict__ out)
{
    const int warp = (blockIdx.x * blockDim.x + threadIdx.x) >> 5;
    if (warp >= N_PTS) return;
    const int n    = warp;
    const int lane = threadIdx.x & 31;
    const int c0   = lane * 2;

    const float2 xv = *(const float2*)(x + (size_t)n * CH + c0);
    const float pix = pos[n * 3 + 0];
    const float piy = pos[n * 3 + 1];
    const float piz = pos[n * 3 + 2];

    const int* eiN = ei + (size_t)n * KMAX;

    float2 best = make_float2(NEG_BIG, NEG_BIG);

    #pragma unroll
    for (int b = 0; b < NBR; b++) {
        const int dil = 1 << b;   // 1, 2, 4

        // A_i = pos_i @ Wp[b] + bp[b]  for this lane's two channels
        const float* Wpb = Wp + b * 3 * CH;
        const float2 w0  = *(const float2*)(Wpb + 0 * CH + c0);
        const float2 w1  = *(const float2*)(Wpb + 1 * CH + c0);
        const float2 w2  = *(const float2*)(Wpb + 2 * CH + c0);
        const float2 bpv = *(const float2*)(bp + b * CH + c0);
        const float Ax = fmaf(pix, w0.x, fmaf(piy, w1.x, fmaf(piz, w2.x, bpv.x)));
        const float Ay = fmaf(pix, w0.y, fmaf(piy, w1.y, fmaf(piz, w2.y, bpv.y)));

        // lanes 0..15 stage neighbor indices
        int j = 0;
        if (lane < KNN) j = eiN[lane * dil];

        float2 sum = make_float2(0.f, 0.f);
        float2 acc = make_float2(0.f, 0.f);

        #pragma unroll
        for (int t = 0; t < KNN; t++) {
            const int jt = __shfl_sync(0xffffffffu, j, t);

            // one 8B load fetches (k',v') for both channels
            const uint2 raw = *(const uint2*)(g_KV + ((size_t)jt * NBR + b) * CH + c0);
            const float2 kv0 = __half22float2(*(const __half2*)&raw.x);  // (k',v') @ c0
            const float2 kv1 = __half22float2(*(const __half2*)&raw.y);  // (k',v') @ c0+1

            const float ex = __expf(Ax - kv0.x);
            const float ey = __expf(Ay - kv1.x);
            sum.x += ex;
            sum.y += ey;
            acc.x = fmaf(ex, kv0.y + Ax, acc.x);
            acc.y = fmaf(ey, kv1.y + Ay, acc.y);
        }

        const float hx = acc.x / (sum.x + 1e-16f);
        const float hy = acc.y / (sum.y + 1e-16f);
        best.x = fmaxf(best.x, hx);
        best.y = fmaxf(best.y, hy);
    }

    const int cloud = batch[n];
    const float2 p = *(const float2*)(g_pool + cloud * CH + c0);

    float2 o;
    o.x = fmaxf(best.x, p.x) + xv.x;
    o.y = fmaxf(best.y, p.y) + xv.y;
    *(float2*)(out + (size_t)n * CH + c0) = o;
}

// ---------------------------------------------------------------------------
// Launch.  Inputs (metadata order):
//  0: x[N*64] f32, 1: pos[N*3] f32, 2: Wv[3*64*64], 3: Wq (UNUSED),
//  4: Wk[3*64*64], 5: Wp[3*3*64], 6: bp[3*64],
//  7: edge_index[2*N*64] i32, 8: batch[N] i32
// ---------------------------------------------------------------------------
extern "C" void kernel_launch(void* const* d_in, const int* in_sizes, int n_in,
                              void* d_out, int out_size)
{
    (void)in_sizes; (void)n_in; (void)out_size;
    const float* x   = (const float*)d_in[0];
    const float* pos = (const float*)d_in[1];
    const float* Wv  = (const float*)d_in[2];
    const float* Wk  = (const float*)d_in[4];
    const float* Wp  = (const float*)d_in[5];
    const float* bp  = (const float*)d_in[6];
    const int*   ei  = (const int*)d_in[7];      // row0 = src
    const int*   bat = (const int*)d_in[8];
    float* out = (float*)d_out;

    dim3 ggrid((N_PTS + 127) / 128, NBR);
    gemm_kv_kernel<<<ggrid, 256>>>(x, pos, Wv, Wk, Wp);

    pool_kernel<<<NCLOUD, 1024>>>(x);

    const int blocks = (N_PTS * 32 + 255) / 256;
    edge_kernel<<<blocks, 256>>>(x, pos, Wp, bp, ei, bat, out);
}